// round 10
// baseline (speedup 1.0000x reference)
#include <cuda_runtime.h>
#include <cstdint>

// ----------------------------------------------------------------------------
// MLPPredictor: score[e] = W * concat(h[src[e]], h[dst[e]]) + b
//   h: [N,5] f32, src/dst: [E] int64 (or int32 — detected), W: [16,10], b:[16]
//   out: [E,16] f32
//
// R10: 1 edge/thread revisited. With weights on the constant port (LDCU,
//      uniform pipe) the 2-edge LDS-amortization rationale is gone; 1 edge
//      per thread has IDENTICAL L1tex wavefronts/edge but a ~40-reg live set,
//      unlocking 6 CTAs/SM (48 warps, was 32) for latency cover.
//      Keeps: 32B padded rows + v8 gathers, phase-split accs, f32x2 math,
//      256-bit stores, fused prep + constant-bank staging.
// ----------------------------------------------------------------------------

#define MAX_NODES 100000
__device__ __align__(32) float g_hp[MAX_NODES * 8];  // padded rows, 32B each

// Staging + constant bank: [0..79] = W pairs, [80..87] = bias pairs,
// [88] = idx64 flag.  cWB[p*10+k] = (W[2p][k], W[2p+1][k]).
__device__ unsigned long long g_wpack[89];
__constant__ unsigned long long cWB[89];

__device__ __forceinline__ unsigned long long pack2f(float lo, float hi) {
    unsigned long long v;
    asm("mov.b64 %0, {%1, %2};" : "=l"(v) : "f"(lo), "f"(hi));
    return v;
}

// Fused prep: pack h [n,5] -> g_hp [n,8]; block 0 additionally packs W/bias
// pairs and detects index width (256 hi-word samples all zero => int64).
__global__ void prep_kernel(const float* __restrict__ h,
                            const float* __restrict__ W,
                            const float* __restrict__ bias,
                            const unsigned int* __restrict__ src_raw,
                            int n_nodes) {
    if (blockIdx.x == 0) {
        int t = threadIdx.x;
        if (t < 80) {
            int p = t / 10, k = t % 10;
            g_wpack[t] = pack2f(W[(2 * p) * 10 + k], W[(2 * p + 1) * 10 + k]);
        } else if (t < 88) {
            int p = t - 80;
            g_wpack[t] = pack2f(bias[2 * p], bias[2 * p + 1]);
        } else if (t >= 96 && t < 128) {
            int l = t - 96;
            unsigned int acc = 0;
#pragma unroll
            for (int j = 0; j < 8; j++)
                acc |= src_raw[2 * (l * 8 + j) + 1];
            unsigned int any = __ballot_sync(0xffffffffu, acc != 0);
            if (l == 0) g_wpack[88] = (any == 0) ? 1ull : 0ull;
        }
    }
    int i = blockIdx.x * blockDim.x + threadIdx.x;
    if (i < n_nodes) {
        const float* r = h + (size_t)i * 5;
        float4 a = make_float4(r[0], r[1], r[2], r[3]);
        float4 b = make_float4(r[4], 0.f, 0.f, 0.f);
        float4* d = reinterpret_cast<float4*>(g_hp + (size_t)i * 8);
        d[0] = a;
        d[1] = b;
    }
}

// 32B gather from a 32B-aligned row (one scattered L1tex pass).
__device__ __forceinline__ void gather8(const float* p, float* r) {
    asm("ld.global.nc.v8.f32 {%0,%1,%2,%3,%4,%5,%6,%7}, [%8];"
        : "=f"(r[0]), "=f"(r[1]), "=f"(r[2]), "=f"(r[3]),
          "=f"(r[4]), "=f"(r[5]), "=f"(r[6]), "=f"(r[7])
        : "l"(p));
}

__device__ __forceinline__ void store32(float* p, const unsigned long long* a) {
    asm volatile("st.global.v4.b64 [%0], {%1,%2,%3,%4};"
                 :: "l"(p), "l"(a[0]), "l"(a[1]), "l"(a[2]), "l"(a[3])
                 : "memory");
}

__global__ __launch_bounds__(256, 6) void edge_mlp_kernel(
    const char* __restrict__ src_raw,
    const char* __restrict__ dst_raw,
    float* __restrict__ out,         // [E,16]
    int E)
{
    unsigned e = blockIdx.x * 256u + threadIdx.x;
    if (e >= (unsigned)E) return;

    // Index width: int64 -> stride 8 (little-endian low word), int32 -> 4.
    unsigned shift = (cWB[88] != 0) ? 3u : 2u;
    unsigned s = *(const unsigned*)(src_raw + ((size_t)e << shift));
    unsigned d = *(const unsigned*)(dst_raw + ((size_t)e << shift));

    float u[8], v[8];
    gather8(g_hp + (size_t)s * 8, u);
    gather8(g_hp + (size_t)d * 8, v);

    float f[10] = {u[0], u[1], u[2], u[3], u[4],
                   v[0], v[1], v[2], v[3], v[4]};

    float* o = out + (size_t)e * 16;

    // Two phases: classes [0,8) then [8,16). 4 class-pairs per phase.
#pragma unroll
    for (int ph = 0; ph < 2; ph++) {
        const int pb = ph * 4;
        unsigned long long acc[4];
#pragma unroll
        for (int p = 0; p < 4; p++) acc[p] = cWB[80 + pb + p];

#pragma unroll
        for (int j = 0; j < 5; j++) {
            const int ka = 2 * j;
            unsigned long long ha, hb;
            asm("mov.b64 %0, {%1, %1};" : "=l"(ha) : "f"(f[ka]));
            asm("mov.b64 %0, {%1, %1};" : "=l"(hb) : "f"(f[ka + 1]));
#pragma unroll
            for (int p = 0; p < 4; p++) {
                unsigned long long wa = cWB[(pb + p) * 10 + ka];
                unsigned long long wb = cWB[(pb + p) * 10 + ka + 1];
                asm("fma.rn.f32x2 %0, %1, %2, %0;" : "+l"(acc[p]) : "l"(wa), "l"(ha));
                asm("fma.rn.f32x2 %0, %1, %2, %0;" : "+l"(acc[p]) : "l"(wb), "l"(hb));
            }
        }

        store32(o + ph * 8, acc);
    }
}

extern "C" void kernel_launch(void* const* d_in, const int* in_sizes, int n_in,
                              void* d_out, int out_size) {
    const float* h  = (const float*)d_in[0];
    const char* src = (const char*)d_in[1];
    const char* dst = (const char*)d_in[2];
    const float* W  = (const float*)d_in[3];
    const float* b  = (const float*)d_in[4];
    float* out = (float*)d_out;

    int n_nodes = in_sizes[0] / 5;
    int E = in_sizes[1];

    prep_kernel<<<(n_nodes + 255) / 256, 256>>>(h, W, b,
                                                (const unsigned int*)src,
                                                n_nodes);

    // Stage packed weights + idx flag into the constant bank (D2D, capturable).
    void* wsrc = nullptr;
    cudaGetSymbolAddress(&wsrc, g_wpack);
    cudaMemcpyToSymbolAsync(cWB, wsrc, 89 * sizeof(unsigned long long), 0,
                            cudaMemcpyDeviceToDevice, 0);

    edge_mlp_kernel<<<(E + 255) / 256, 256>>>(src, dst, out, E);
}